// round 12
// baseline (speedup 1.0000x reference)
#include <cuda_runtime.h>
#include <cuda_bf16.h>
#include <cstddef>
#include <cstdint>

#define BB 8
#define CC 256
#define NN 4096            // tokens
#define GG 32
#define CPG 8

// ---------------- scratch (device globals: allocation-free) ----------------
__device__ float g_h[(size_t)BB * CC * NN];                     // normalized input
__device__ float g_qkv[(size_t)BB * 3 * CC * NN];               // fp32 q,k,v [b][o][n]
__device__ __nv_bfloat16 g_qb[(size_t)BB * NN * CC];            // Q  [b][q][c] (scaled)
__device__ __nv_bfloat16 g_kb[(size_t)BB * NN * CC];            // K  [b][k][c]
__device__ __nv_bfloat16 g_vb[(size_t)BB * CC * NN];            // V  [b][c][k]
__device__ float g_att[(size_t)BB * CC * NN];                   // attention out

// ============================ helpers =======================================
__device__ __forceinline__ uint32_t smem_u32(const void* p) {
    uint32_t a;
    asm("{ .reg .u64 t; cvta.to.shared.u64 t, %1; cvt.u32.u64 %0, t; }"
        : "=r"(a) : "l"(p));
    return a;
}
__device__ __forceinline__ uint32_t pack_bf16x2(float lo, float hi) {
    uint32_t r;
    asm("cvt.rn.bf16x2.f32 %0, %1, %2;" : "=r"(r) : "f"(hi), "f"(lo));
    return r;
}
__device__ __forceinline__ float ex2f(float x) {
    float r;
    asm("ex2.approx.ftz.f32 %0, %1;" : "=f"(r) : "f"(x));
    return r;
}
__device__ __forceinline__ void ldsm_x4(uint32_t& r0, uint32_t& r1,
                                        uint32_t& r2, uint32_t& r3, uint32_t a) {
    asm volatile("ldmatrix.sync.aligned.m8n8.x4.shared.b16 {%0,%1,%2,%3}, [%4];"
                 : "=r"(r0), "=r"(r1), "=r"(r2), "=r"(r3) : "r"(a));
}
__device__ __forceinline__ void mma_bf16(float4& d,
                                         uint32_t a0, uint32_t a1, uint32_t a2, uint32_t a3,
                                         uint32_t b0, uint32_t b1) {
    asm volatile(
        "mma.sync.aligned.m16n8k16.row.col.f32.bf16.bf16.f32 "
        "{%0,%1,%2,%3}, {%4,%5,%6,%7}, {%8,%9}, {%0,%1,%2,%3};"
        : "+f"(d.x), "+f"(d.y), "+f"(d.z), "+f"(d.w)
        : "r"(a0), "r"(a1), "r"(a2), "r"(a3), "r"(b0), "r"(b1));
}
#define CP_ASYNC16(dst, src) \
    asm volatile("cp.async.cg.shared.global [%0], [%1], 16;" \
                 :: "r"(dst), "l"(src) : "memory")
#define CP_COMMIT() asm volatile("cp.async.commit_group;" ::: "memory")
#define CP_WAIT(n)  asm volatile("cp.async.wait_group %0;" :: "n"(n) : "memory")

// ============================ GroupNorm =====================================
__global__ void __launch_bounds__(256) gn_kernel(const float* __restrict__ x,
                                                 const float* __restrict__ w,
                                                 const float* __restrict__ bg,
                                                 float* __restrict__ h)
{
    const int g = blockIdx.x, b = blockIdx.y;
    const size_t base = ((size_t)b * CC + (size_t)g * CPG) * NN;
    const float* xp = x + base;
    float* hp = h + base;
    const int tid = threadIdx.x;

    float s = 0.f, ss = 0.f;
#pragma unroll
    for (int t = 0; t < 32; t++) {
        float4 v = *reinterpret_cast<const float4*>(xp + (size_t)(t * 256 + tid) * 4);
        s  += v.x + v.y + v.z + v.w;
        ss += v.x * v.x + v.y * v.y + v.z * v.z + v.w * v.w;
    }
#pragma unroll
    for (int o = 16; o; o >>= 1) {
        s  += __shfl_xor_sync(0xffffffffu, s, o);
        ss += __shfl_xor_sync(0xffffffffu, ss, o);
    }
    __shared__ float rs[8], rss[8], stats[2];
    if ((tid & 31) == 0) { rs[tid >> 5] = s; rss[tid >> 5] = ss; }
    __syncthreads();
    if (tid == 0) {
        float ts = 0.f, tss = 0.f;
#pragma unroll
        for (int i = 0; i < 8; i++) { ts += rs[i]; tss += rss[i]; }
        const float inv_n = 1.0f / (CPG * NN);
        float mu = ts * inv_n;
        float var = tss * inv_n - mu * mu;
        stats[0] = mu;
        stats[1] = rsqrtf(var + 1e-5f);
    }
    __syncthreads();
    const float mu = stats[0], rsg = stats[1];
#pragma unroll
    for (int t = 0; t < 32; t++) {
        const int idx = (t * 256 + tid) * 4;
        const int c = g * CPG + (idx >> 12);
        const float sc = w[c] * rsg;
        const float sh = bg[c] - mu * sc;
        float4 v = *reinterpret_cast<const float4*>(xp + idx);
        v.x = v.x * sc + sh; v.y = v.y * sc + sh;
        v.z = v.z * sc + sh; v.w = v.w * sc + sh;
        *reinterpret_cast<float4*>(hp + idx) = v;
    }
}

// =================== tiled SGEMM (verified; qkv + proj) =====================
__global__ void __launch_bounds__(256) gemm_kernel(const float* __restrict__ W,
                                                   const float* __restrict__ X,
                                                   const float* __restrict__ bias,
                                                   const float* __restrict__ resid,
                                                   float* __restrict__ out,
                                                   int M)
{
    const int K = 256, N = NN;
    __shared__ float sW[16 * 65];
    __shared__ float sX[16 * 64];

    const int tid = threadIdx.x;
    const int tx = tid & 15, ty = tid >> 4;
    const int n0 = blockIdx.x * 64, m0 = blockIdx.y * 64, b = blockIdx.z;
    const float* Xb = X + (size_t)b * K * N;

    float4 acc[4];
#pragma unroll
    for (int i = 0; i < 4; i++) acc[i] = make_float4(0.f, 0.f, 0.f, 0.f);

    for (int k0 = 0; k0 < K; k0 += 16) {
#pragma unroll
        for (int t = 0; t < 4; t++) {
            int idx = tid + t * 256;
            int o = idx >> 4, k = idx & 15;
            sW[k * 65 + o] = W[(size_t)(m0 + o) * K + k0 + k];
        }
#pragma unroll
        for (int t = 0; t < 4; t++) {
            int idx = tid + t * 256;
            int k = idx >> 6, n = idx & 63;
            sX[k * 64 + n] = Xb[(size_t)(k0 + k) * N + n0 + n];
        }
        __syncthreads();
#pragma unroll
        for (int kk = 0; kk < 16; kk++) {
            float4 xv = *reinterpret_cast<float4*>(sX + kk * 64 + tx * 4);
            float a0 = sW[kk * 65 + ty * 4 + 0];
            float a1 = sW[kk * 65 + ty * 4 + 1];
            float a2 = sW[kk * 65 + ty * 4 + 2];
            float a3 = sW[kk * 65 + ty * 4 + 3];
            acc[0].x += a0 * xv.x; acc[0].y += a0 * xv.y; acc[0].z += a0 * xv.z; acc[0].w += a0 * xv.w;
            acc[1].x += a1 * xv.x; acc[1].y += a1 * xv.y; acc[1].z += a1 * xv.z; acc[1].w += a1 * xv.w;
            acc[2].x += a2 * xv.x; acc[2].y += a2 * xv.y; acc[2].z += a2 * xv.z; acc[2].w += a2 * xv.w;
            acc[3].x += a3 * xv.x; acc[3].y += a3 * xv.y; acc[3].z += a3 * xv.z; acc[3].w += a3 * xv.w;
        }
        __syncthreads();
    }
#pragma unroll
    for (int i = 0; i < 4; i++) {
        const int o = m0 + ty * 4 + i;
        const float bv = bias[o];
        float4 r = acc[i];
        r.x += bv; r.y += bv; r.z += bv; r.w += bv;
        const size_t off = ((size_t)b * M + o) * N + n0 + tx * 4;
        if (resid) {
            float4 rv = *reinterpret_cast<const float4*>(resid + off);
            r.x += rv.x; r.y += rv.y; r.z += rv.z; r.w += rv.w;
        }
        *reinterpret_cast<float4*>(out + off) = r;
    }
}

// ============ fp32 qkv -> bf16 operand buffers (transpose q/k) ==============
__global__ void __launch_bounds__(256) conv_kernel(const float* __restrict__ qkv,
                                                   __nv_bfloat16* __restrict__ qb,
                                                   __nv_bfloat16* __restrict__ kb,
                                                   __nv_bfloat16* __restrict__ vb)
{
    __shared__ float tile[32][33];
    const int b = blockIdx.z / 3, which = blockIdx.z % 3;
    const int n0 = blockIdx.x * 32, c0 = blockIdx.y * 32;
    const int tx = threadIdx.x & 31, ty = threadIdx.x >> 5;   // 32 x 8

    const float* src = qkv + ((size_t)b * 3 * CC + which * CC) * NN;
#pragma unroll
    for (int i = 0; i < 4; i++) {
        int c = c0 + ty + i * 8;
        tile[ty + i * 8][tx] = src[(size_t)c * NN + n0 + tx];
    }
    __syncthreads();

    if (which == 2) {
#pragma unroll
        for (int i = 0; i < 4; i++) {
            int c = c0 + ty + i * 8;
            vb[((size_t)b * CC + c) * NN + n0 + tx] =
                __float2bfloat16(tile[ty + i * 8][tx]);
        }
    } else {
        const float scl = (which == 0) ? 0.09016844f : 1.0f;  // log2(e)/16
        __nv_bfloat16* dst = (which == 0) ? qb : kb;
#pragma unroll
        for (int i = 0; i < 4; i++) {
            int n = n0 + ty + i * 8;
            dst[((size_t)b * NN + n) * CC + c0 + tx] =
                __float2bfloat16(tile[tx][ty + i * 8] * scl);
        }
    }
}

// ==== flash attention: bf16 m16n8k16, ldmatrix.x4, cp.async double buffer ===
// CTA: 128 q, 8 warps (warp = 16 q x 64 keys x 256 channels), 64-key tiles.
// ldmatrix.x4 matrix map (addr = base + lrow*stride + loff):
//   r0=(rows0-7,first16B) r1=(rows8-15,first16B) r2=(rows0-7,+16B) r3=(rows8-15,+16B)
// A-frag = (r0,r1,r2,r3); B-frag pairs = (r0,r2) and (r1,r3).   [validated R9/R11]
#define QSTB 528                          // 256 bf16 + 16B pad
#define VSTB 144                          // 64 bf16 + 16B pad
#define SQ_OFF 0
#define SK_OFF  (128 * QSTB)              // 67584
#define SK_BUF  (64 * QSTB)               // 33792
#define SV_OFF  (SK_OFF + 2 * SK_BUF)     // 135168
#define SV_BUF  (256 * VSTB)              // 36864
#define ATT_SMEM (SV_OFF + 2 * SV_BUF)    // 208896

__global__ void __launch_bounds__(256, 1) attn5_kernel(const __nv_bfloat16* __restrict__ qb,
                                                       const __nv_bfloat16* __restrict__ kb,
                                                       const __nv_bfloat16* __restrict__ vb,
                                                       float* __restrict__ outp)
{
    extern __shared__ char sm[];
    const uint32_t sbase = smem_u32(sm);

    const int tid  = threadIdx.x;
    const int lane = tid & 31;
    const int wid  = tid >> 5;
    const int b    = blockIdx.y;
    const int q0   = blockIdx.x * 128;

    const __nv_bfloat16* Qg = qb + ((size_t)b * NN + q0) * 256;
    const __nv_bfloat16* Kg = kb + (size_t)b * NN * 256;
    const __nv_bfloat16* Vg = vb + (size_t)b * CC * NN;

    // ---- load Q tile: [128][256] bf16, row stride 528B ----
#pragma unroll
    for (int tt = 0; tt < 16; tt++) {
        int idx = tid + tt * 256;          // 16B chunks
        int r = idx >> 5, ch = idx & 31;
        *reinterpret_cast<uint4*>(sm + SQ_OFF + r * QSTB + ch * 16) =
            *reinterpret_cast<const uint4*>(Qg + (size_t)r * 256 + ch * 8);
    }

    // per-thread cp.async slices (8 x 16B each for K and V)
    const int kr = tid >> 5, kch = tid & 31;           // K: rows kr,kr+8,.. ch kch
    const int vc = tid >> 3, vch = tid & 7;            // V: cols.. c vc,vc+32.. ch vch

    // prologue: prefetch tile 0 into buffer 0
    {
        const uint32_t kd = sbase + SK_OFF;
        const uint32_t vd = sbase + SV_OFF;
#pragma unroll
        for (int tt = 0; tt < 8; tt++) {
            int r = kr + tt * 8;
            CP_ASYNC16(kd + r * QSTB + kch * 16, Kg + (size_t)r * 256 + kch * 8);
        }
#pragma unroll
        for (int tt = 0; tt < 8; tt++) {
            int c = vc + tt * 32;
            CP_ASYNC16(vd + c * VSTB + vch * 16, Vg + (size_t)c * NN + vch * 8);
        }
        CP_COMMIT();
    }

    // ldmatrix lane mapping
    const int lrow = ((lane >> 3) & 1) * 8 + (lane & 7);
    const int loff = ((lane >> 4) & 1) * 16;
    const uint32_t aQ = sbase + SQ_OFF + (wid * 16 + lrow) * QSTB + loff;

    float4 oacc[32];
#pragma unroll
    for (int j = 0; j < 32; j++) oacc[j] = make_float4(0.f, 0.f, 0.f, 0.f);
    float m0r = -1e30f, m1r = -1e30f, l0r = 0.f, l1r = 0.f;

    for (int kt = 0; kt < 64; kt++) {
        const int cur = kt & 1;
        // prefetch next tile into the other buffer (its prior readers finished
        // at the end-of-iteration barrier of iter kt-1)
        if (kt < 63) {
            const int k0n = (kt + 1) * 64;
            const uint32_t kd = sbase + SK_OFF + (cur ^ 1) * SK_BUF;
            const uint32_t vd = sbase + SV_OFF + (cur ^ 1) * SV_BUF;
#pragma unroll
            for (int tt = 0; tt < 8; tt++) {
                int r = kr + tt * 8;
                CP_ASYNC16(kd + r * QSTB + kch * 16,
                           Kg + (size_t)(k0n + r) * 256 + kch * 8);
            }
#pragma unroll
            for (int tt = 0; tt < 8; tt++) {
                int c = vc + tt * 32;
                CP_ASYNC16(vd + c * VSTB + vch * 16,
                           Vg + (size_t)c * NN + k0n + vch * 8);
            }
            CP_COMMIT();
            CP_WAIT(1);                    // tile kt complete (newest pending)
        } else {
            CP_WAIT(0);
        }
        __syncthreads();                   // tile kt visible to all warps

        const uint32_t bK = sbase + SK_OFF + cur * SK_BUF + lrow * QSTB + loff;
        const uint32_t bV = sbase + SV_OFF + cur * SV_BUF + lrow * VSTB + loff;

        // ---- S = Q K^T : warp 16q x 64k, K-dim 256 ----
        float4 d[8];
#pragma unroll
        for (int j = 0; j < 8; j++) d[j] = make_float4(0.f, 0.f, 0.f, 0.f);
#pragma unroll 4
        for (int kc = 0; kc < 16; kc++) {
            uint32_t a0, a1, a2, a3;
            ldsm_x4(a0, a1, a2, a3, aQ + kc * 32);
#pragma unroll
            for (int ng = 0; ng < 4; ng++) {
                uint32_t b0, b1, b2, b3;
                ldsm_x4(b0, b1, b2, b3, bK + ng * (16 * QSTB) + kc * 32);
                mma_bf16(d[2 * ng],     a0, a1, a2, a3, b0, b2);
                mma_bf16(d[2 * ng + 1], a0, a1, a2, a3, b1, b3);
            }
        }

        // ---- online softmax (S in log2 units; Q pre-scaled by log2e/16) ----
        float nm0 = -1e30f, nm1 = -1e30f;
#pragma unroll
        for (int j = 0; j < 8; j++) {
            nm0 = fmaxf(nm0, fmaxf(d[j].x, d[j].y));
            nm1 = fmaxf(nm1, fmaxf(d[j].z, d[j].w));
        }
        nm0 = fmaxf(nm0, __shfl_xor_sync(0xffffffffu, nm0, 1));
        nm0 = fmaxf(nm0, __shfl_xor_sync(0xffffffffu, nm0, 2));
        nm1 = fmaxf(nm1, __shfl_xor_sync(0xffffffffu, nm1, 1));
        nm1 = fmaxf(nm1, __shfl_xor_sync(0xffffffffu, nm1, 2));
        nm0 = fmaxf(m0r, nm0);
        nm1 = fmaxf(m1r, nm1);
        const float al0 = ex2f(m0r - nm0);
        const float al1 = ex2f(m1r - nm1);
        m0r = nm0; m1r = nm1;

        uint32_t pa[4][4];
        float ls0 = 0.f, ls1 = 0.f;
#pragma unroll
        for (int kc = 0; kc < 4; kc++) {
            float p00 = ex2f(d[2 * kc].x - nm0), p01 = ex2f(d[2 * kc].y - nm0);
            float p02 = ex2f(d[2 * kc].z - nm1), p03 = ex2f(d[2 * kc].w - nm1);
            float p10 = ex2f(d[2 * kc + 1].x - nm0), p11 = ex2f(d[2 * kc + 1].y - nm0);
            float p12 = ex2f(d[2 * kc + 1].z - nm1), p13 = ex2f(d[2 * kc + 1].w - nm1);
            ls0 += (p00 + p01) + (p10 + p11);
            ls1 += (p02 + p03) + (p12 + p13);
            pa[kc][0] = pack_bf16x2(p00, p01);
            pa[kc][1] = pack_bf16x2(p02, p03);
            pa[kc][2] = pack_bf16x2(p10, p11);
            pa[kc][3] = pack_bf16x2(p12, p13);
        }
        l0r = l0r * al0 + ls0;             // per-thread 16-key partial
        l1r = l1r * al1 + ls1;

        // rescale O only when max moved (warp-uniform check)
        if (!__all_sync(0xffffffffu, (al0 == 1.f) & (al1 == 1.f))) {
#pragma unroll
            for (int j = 0; j < 32; j++) {
                oacc[j].x *= al0; oacc[j].y *= al0;
                oacc[j].z *= al1; oacc[j].w *= al1;
            }
        }

        // ---- O += P V^T : warp 16q x 256c, K-dim 64 ----
#pragma unroll 4
        for (int cg = 0; cg < 16; cg++) {
#pragma unroll
            for (int kc = 0; kc < 4; kc++) {
                uint32_t b0, b1, b2, b3;
                ldsm_x4(b0, b1, b2, b3, bV + cg * (16 * VSTB) + kc * 32);
                mma_bf16(oacc[2 * cg],     pa[kc][0], pa[kc][1], pa[kc][2], pa[kc][3], b0, b2);
                mma_bf16(oacc[2 * cg + 1], pa[kc][0], pa[kc][1], pa[kc][2], pa[kc][3], b1, b3);
            }
        }
        __syncthreads();                   // all done reading tile kt
    }

    // ---- combine the 4 per-lane l partials of each row ----
    l0r += __shfl_xor_sync(0xffffffffu, l0r, 1);
    l0r += __shfl_xor_sync(0xffffffffu, l0r, 2);
    l1r += __shfl_xor_sync(0xffffffffu, l1r, 1);
    l1r += __shfl_xor_sync(0xffffffffu, l1r, 2);

    // ---- epilogue: O / l -> out[c][q] ----
    const float inv0 = __frcp_rn(l0r);
    const float inv1 = __frcp_rn(l1r);
    const int g = lane >> 2, t = lane & 3;
    const int qr0 = q0 + wid * 16 + g;
    const int qr1 = qr0 + 8;
    const int cbase = t * 2;
#pragma unroll
    for (int j = 0; j < 32; j++) {
        const int c = 8 * j + cbase;
        float* bp = outp + ((size_t)b * CC + c) * NN;
        bp[qr0]      = oacc[j].x * inv0;
        bp[NN + qr0] = oacc[j].y * inv0;
        bp[qr1]      = oacc[j].z * inv1;
        bp[NN + qr1] = oacc[j].w * inv1;
    }
}

// ================================ launch ====================================
extern "C" void kernel_launch(void* const* d_in, const int* in_sizes, int n_in,
                              void* d_out, int out_size)
{
    const float* x     = (const float*)d_in[0];
    const float* nw    = (const float*)d_in[1];
    const float* nb    = (const float*)d_in[2];
    const float* qkvw  = (const float*)d_in[3];
    const float* qkvb  = (const float*)d_in[4];
    const float* projw = (const float*)d_in[5];
    const float* projb = (const float*)d_in[6];
    float* out = (float*)d_out;

    float *hbuf, *qkvbuf, *abuf;
    __nv_bfloat16 *qbp, *kbp, *vbp;
    cudaGetSymbolAddress((void**)&hbuf, g_h);
    cudaGetSymbolAddress((void**)&qkvbuf, g_qkv);
    cudaGetSymbolAddress((void**)&abuf, g_att);
    cudaGetSymbolAddress((void**)&qbp, g_qb);
    cudaGetSymbolAddress((void**)&kbp, g_kb);
    cudaGetSymbolAddress((void**)&vbp, g_vb);

    cudaFuncSetAttribute(attn5_kernel, cudaFuncAttributeMaxDynamicSharedMemorySize,
                         ATT_SMEM);

    gn_kernel<<<dim3(GG, BB), 256>>>(x, nw, nb, hbuf);
    gemm_kernel<<<dim3(NN / 64, 12, BB), 256>>>(qkvw, hbuf, qkvb, nullptr,
                                                qkvbuf, 3 * CC);
    conv_kernel<<<dim3(NN / 32, CC / 32, BB * 3), 256>>>(qkvbuf, qbp, kbp, vbp);
    attn5_kernel<<<dim3(NN / 128, BB), 256, ATT_SMEM>>>(qbp, kbp, vbp, abuf);
    gemm_kernel<<<dim3(NN / 64, CC / 64, BB), 256>>>(projw, abuf, projb, x, out, CC);
}

// round 13
// speedup vs baseline: 1.3850x; 1.3850x over previous
#include <cuda_runtime.h>
#include <cuda_bf16.h>
#include <cstddef>
#include <cstdint>

#define BB 8
#define CC 256
#define NN 4096            // tokens
#define GG 32
#define CPG 8

// ---------------- scratch (device globals: allocation-free) ----------------
__device__ float g_h[(size_t)BB * CC * NN];                     // normalized input (fp32)
__device__ __nv_bfloat16 g_ht[(size_t)BB * NN * CC];            // h^T bf16 [b][n][c]
__device__ __nv_bfloat16 g_wq[768 * 256];                       // qkv_w bf16
__device__ __nv_bfloat16 g_wp[256 * 256];                       // proj_w bf16
__device__ __nv_bfloat16 g_qb[(size_t)BB * NN * CC];            // Q [b][q][c] (scaled)
__device__ __nv_bfloat16 g_kb[(size_t)BB * NN * CC];            // K [b][k][c]
__device__ __nv_bfloat16 g_vb[(size_t)BB * CC * NN];            // V [b][c][k]
__device__ __nv_bfloat16 g_ob[(size_t)BB * NN * CC];            // attn out [b][n][c]

// ============================ helpers =======================================
__device__ __forceinline__ uint32_t smem_u32(const void* p) {
    uint32_t a;
    asm("{ .reg .u64 t; cvta.to.shared.u64 t, %1; cvt.u32.u64 %0, t; }"
        : "=r"(a) : "l"(p));
    return a;
}
__device__ __forceinline__ uint32_t pack_bf16x2(float lo, float hi) {
    uint32_t r;
    asm("cvt.rn.bf16x2.f32 %0, %1, %2;" : "=r"(r) : "f"(hi), "f"(lo));
    return r;
}
__device__ __forceinline__ float ex2f(float x) {
    float r;
    asm("ex2.approx.ftz.f32 %0, %1;" : "=f"(r) : "f"(x));
    return r;
}
__device__ __forceinline__ void ldsm_x4(uint32_t& r0, uint32_t& r1,
                                        uint32_t& r2, uint32_t& r3, uint32_t a) {
    asm volatile("ldmatrix.sync.aligned.m8n8.x4.shared.b16 {%0,%1,%2,%3}, [%4];"
                 : "=r"(r0), "=r"(r1), "=r"(r2), "=r"(r3) : "r"(a));
}
__device__ __forceinline__ void mma_bf16(float4& d,
                                         uint32_t a0, uint32_t a1, uint32_t a2, uint32_t a3,
                                         uint32_t b0, uint32_t b1) {
    asm volatile(
        "mma.sync.aligned.m16n8k16.row.col.f32.bf16.bf16.f32 "
        "{%0,%1,%2,%3}, {%4,%5,%6,%7}, {%8,%9}, {%0,%1,%2,%3};"
        : "+f"(d.x), "+f"(d.y), "+f"(d.z), "+f"(d.w)
        : "r"(a0), "r"(a1), "r"(a2), "r"(a3), "r"(b0), "r"(b1));
}
#define CP_ASYNC16(dst, src) \
    asm volatile("cp.async.cg.shared.global [%0], [%1], 16;" \
                 :: "r"(dst), "l"(src) : "memory")
#define CP_COMMIT() asm volatile("cp.async.commit_group;" ::: "memory")
#define CP_WAIT(n)  asm volatile("cp.async.wait_group %0;" :: "n"(n) : "memory")

// ============================ GroupNorm =====================================
__global__ void __launch_bounds__(256) gn_kernel(const float* __restrict__ x,
                                                 const float* __restrict__ w,
                                                 const float* __restrict__ bg,
                                                 float* __restrict__ h)
{
    const int g = blockIdx.x, b = blockIdx.y;
    const size_t base = ((size_t)b * CC + (size_t)g * CPG) * NN;
    const float* xp = x + base;
    float* hp = h + base;
    const int tid = threadIdx.x;

    float s = 0.f, ss = 0.f;
#pragma unroll
    for (int t = 0; t < 32; t++) {
        float4 v = *reinterpret_cast<const float4*>(xp + (size_t)(t * 256 + tid) * 4);
        s  += v.x + v.y + v.z + v.w;
        ss += v.x * v.x + v.y * v.y + v.z * v.z + v.w * v.w;
    }
#pragma unroll
    for (int o = 16; o; o >>= 1) {
        s  += __shfl_xor_sync(0xffffffffu, s, o);
        ss += __shfl_xor_sync(0xffffffffu, ss, o);
    }
    __shared__ float rs[8], rss[8], stats[2];
    if ((tid & 31) == 0) { rs[tid >> 5] = s; rss[tid >> 5] = ss; }
    __syncthreads();
    if (tid == 0) {
        float ts = 0.f, tss = 0.f;
#pragma unroll
        for (int i = 0; i < 8; i++) { ts += rs[i]; tss += rss[i]; }
        const float inv_n = 1.0f / (CPG * NN);
        float mu = ts * inv_n;
        float var = tss * inv_n - mu * mu;
        stats[0] = mu;
        stats[1] = rsqrtf(var + 1e-5f);
    }
    __syncthreads();
    const float mu = stats[0], rsg = stats[1];
#pragma unroll
    for (int t = 0; t < 32; t++) {
        const int idx = (t * 256 + tid) * 4;
        const int c = g * CPG + (idx >> 12);
        const float sc = w[c] * rsg;
        const float sh = bg[c] - mu * sc;
        float4 v = *reinterpret_cast<const float4*>(xp + idx);
        v.x = v.x * sc + sh; v.y = v.y * sc + sh;
        v.z = v.z * sc + sh; v.w = v.w * sc + sh;
        *reinterpret_cast<float4*>(hp + idx) = v;
    }
}

// =================== weight fp32 -> bf16 convert ============================
__global__ void __launch_bounds__(256) wconv_kernel(const float* __restrict__ qkvw,
                                                    const float* __restrict__ projw,
                                                    __nv_bfloat16* __restrict__ wq,
                                                    __nv_bfloat16* __restrict__ wp)
{
    int idx = blockIdx.x * 256 + threadIdx.x;
    if (idx < 768 * 256) wq[idx] = __float2bfloat16(qkvw[idx]);
    else                 wp[idx - 768 * 256] = __float2bfloat16(projw[idx - 768 * 256]);
}

// ========== h fp32 [b][c][n] -> bf16 [b][n][c] transpose ====================
__global__ void __launch_bounds__(256) ht_kernel(const float* __restrict__ h,
                                                 __nv_bfloat16* __restrict__ ht)
{
    __shared__ float tile[32][33];
    const int b = blockIdx.z;
    const int n0 = blockIdx.x * 32, c0 = blockIdx.y * 32;
    const int tx = threadIdx.x & 31, ty = threadIdx.x >> 5;   // 32 x 8

    const float* src = h + (size_t)b * CC * NN;
#pragma unroll
    for (int i = 0; i < 4; i++) {
        int c = c0 + ty + i * 8;
        tile[ty + i * 8][tx] = src[(size_t)c * NN + n0 + tx];
    }
    __syncthreads();
#pragma unroll
    for (int i = 0; i < 4; i++) {
        int n = n0 + ty + i * 8;
        ht[((size_t)b * NN + n) * CC + c0 + tx] = __float2bfloat16(tile[tx][ty + i * 8]);
    }
}

// ================= bf16 tensor GEMM (qkv mode 0 / proj mode 1) ==============
// D[m][n] = sum_k A[m][k] * B[n][k];  A = W bf16 [M][256], B = [b][n][256] bf16.
// CTA: 64 m x 128 n, K = 256 in one smem residency. 8 warps = 4m x 2n,
// warp = 16m x 64n. Fragment conventions identical to attn5 (validated).
#define TG_ST  528                       // 256 bf16 + 16B pad
#define TG_SA  0
#define TG_SB  (64 * TG_ST)              // 33792
#define TG_SMEM ((64 + 128) * TG_ST)     // 101376

__global__ void __launch_bounds__(256) tgemm_kernel(const __nv_bfloat16* __restrict__ A,
                                                    const __nv_bfloat16* __restrict__ Bm,
                                                    const float* __restrict__ bias,
                                                    const float* __restrict__ resid,
                                                    __nv_bfloat16* __restrict__ oq,
                                                    __nv_bfloat16* __restrict__ ok,
                                                    __nv_bfloat16* __restrict__ ov,
                                                    float* __restrict__ ofp,
                                                    int mode)
{
    extern __shared__ char sm[];
    const uint32_t sbase = smem_u32(sm);
    const int tid  = threadIdx.x;
    const int lane = tid & 31;
    const int wid  = tid >> 5;
    const int g    = lane >> 2;
    const int t    = lane & 3;
    const int n0   = blockIdx.x * 128;
    const int m0   = blockIdx.y * 64;
    const int b    = blockIdx.z;

    const __nv_bfloat16* Bb = Bm + (size_t)b * NN * CC;

    // ---- load A tile [64][256] and B tile [128][256] via cp.async ----
#pragma unroll
    for (int tt = 0; tt < 8; tt++) {
        int idx = tid + tt * 256;          // 16B chunks, 2048 total
        int r = idx >> 5, ch = idx & 31;
        CP_ASYNC16(sbase + TG_SA + r * TG_ST + ch * 16,
                   A + (size_t)(m0 + r) * 256 + ch * 8);
    }
#pragma unroll
    for (int tt = 0; tt < 16; tt++) {
        int idx = tid + tt * 256;          // 4096 chunks
        int r = idx >> 5, ch = idx & 31;
        CP_ASYNC16(sbase + TG_SB + r * TG_ST + ch * 16,
                   Bb + (size_t)(n0 + r) * 256 + ch * 8);
    }
    CP_COMMIT();
    CP_WAIT(0);
    __syncthreads();

    const int wm = (wid & 3) * 16;         // warp m offset
    const int wn = (wid >> 2) * 64;        // warp n offset
    const int lrow = ((lane >> 3) & 1) * 8 + (lane & 7);
    const int loff = ((lane >> 4) & 1) * 16;
    const uint32_t aA = sbase + TG_SA + (wm + lrow) * TG_ST + loff;
    const uint32_t bB = sbase + TG_SB + (wn + lrow) * TG_ST + loff;

    float4 d[8];
#pragma unroll
    for (int j = 0; j < 8; j++) d[j] = make_float4(0.f, 0.f, 0.f, 0.f);

#pragma unroll 4
    for (int kc = 0; kc < 16; kc++) {
        uint32_t a0, a1, a2, a3;
        ldsm_x4(a0, a1, a2, a3, aA + kc * 32);
#pragma unroll
        for (int f = 0; f < 4; f++) {
            uint32_t b0, b1, b2, b3;
            ldsm_x4(b0, b1, b2, b3, bB + f * (16 * TG_ST) + kc * 32);
            mma_bf16(d[2 * f],     a0, a1, a2, a3, b0, b2);
            mma_bf16(d[2 * f + 1], a0, a1, a2, a3, b1, b3);
        }
    }

    // D-frag coords: rows m = wm+g / wm+g+8; cols n = wn + (j>>1)*16 + (j&1)*8 + 2t, +1
    const float bv0 = bias[m0 + wm + g];
    const float bv1 = bias[m0 + wm + g + 8];

    if (mode == 1) {
        // proj: fp32 out + bias + residual
        const int o0 = m0 + wm + g, o1 = o0 + 8;
#pragma unroll
        for (int j = 0; j < 8; j++) {
            const int n = n0 + wn + (j >> 1) * 16 + (j & 1) * 8 + 2 * t;
            const float* r0p = resid + ((size_t)b * CC + o0) * NN + n;
            const float* r1p = resid + ((size_t)b * CC + o1) * NN + n;
            float2 rv0 = *reinterpret_cast<const float2*>(r0p);
            float2 rv1 = *reinterpret_cast<const float2*>(r1p);
            float2 w0 = make_float2(d[j].x + bv0 + rv0.x, d[j].y + bv0 + rv0.y);
            float2 w1 = make_float2(d[j].z + bv1 + rv1.x, d[j].w + bv1 + rv1.y);
            *reinterpret_cast<float2*>(ofp + ((size_t)b * CC + o0) * NN + n) = w0;
            *reinterpret_cast<float2*>(ofp + ((size_t)b * CC + o1) * NN + n) = w1;
        }
        return;
    }

    if (m0 >= 512) {
        // v rows: direct bf16 [b][c][n]
        const int o0 = m0 - 512 + wm + g, o1 = o0 + 8;
#pragma unroll
        for (int j = 0; j < 8; j++) {
            const int n = n0 + wn + (j >> 1) * 16 + (j & 1) * 8 + 2 * t;
            *reinterpret_cast<uint32_t*>(ov + ((size_t)b * CC + o0) * NN + n) =
                pack_bf16x2(d[j].x + bv0, d[j].y + bv0);
            *reinterpret_cast<uint32_t*>(ov + ((size_t)b * CC + o1) * NN + n) =
                pack_bf16x2(d[j].z + bv1, d[j].w + bv1);
        }
        return;
    }

    // q/k rows: transpose via smem staging -> [b][n][c] bf16
    const float scl = (m0 < 256) ? 0.09016844f : 1.0f;    // log2(e)/16 for q
    __nv_bfloat16* sT = reinterpret_cast<__nv_bfloat16*>(sm);   // [128 n][72]
    __syncthreads();                        // everyone done reading A/B smem
    {
        const int m_lo = wm + g, m_hi = m_lo + 8;
#pragma unroll
        for (int j = 0; j < 8; j++) {
            const int n = wn + (j >> 1) * 16 + (j & 1) * 8 + 2 * t;
            sT[n * 72 + m_lo]       = __float2bfloat16((d[j].x + bv0) * scl);
            sT[(n + 1) * 72 + m_lo] = __float2bfloat16((d[j].y + bv0) * scl);
            sT[n * 72 + m_hi]       = __float2bfloat16((d[j].z + bv1) * scl);
            sT[(n + 1) * 72 + m_hi] = __float2bfloat16((d[j].w + bv1) * scl);
        }
    }
    __syncthreads();
    __nv_bfloat16* dst = (m0 < 256) ? oq : ok;
    const int mo = (m0 < 256) ? m0 : m0 - 256;
#pragma unroll
    for (int cidx = 0; cidx < 4; cidx++) {
        int idx = tid + cidx * 256;         // 1024 16B chunks
        int n = idx >> 3, seg = idx & 7;
        uint4 v = *reinterpret_cast<uint4*>(sT + n * 72 + seg * 8);
        *reinterpret_cast<uint4*>(dst + ((size_t)b * NN + n0 + n) * CC + mo + seg * 8) = v;
    }
}

// ==== flash attention: bf16 m16n8k16, ldmatrix.x4, cp.async double buffer ===
#define QSTB 528
#define VSTB 144
#define SQ_OFF 0
#define SK_OFF  (128 * QSTB)
#define SK_BUF  (64 * QSTB)
#define SV_OFF  (SK_OFF + 2 * SK_BUF)
#define SV_BUF  (256 * VSTB)
#define ATT_SMEM (SV_OFF + 2 * SV_BUF)     // 208896

__global__ void __launch_bounds__(256, 1) attn5_kernel(const __nv_bfloat16* __restrict__ qb,
                                                       const __nv_bfloat16* __restrict__ kb,
                                                       const __nv_bfloat16* __restrict__ vb,
                                                       __nv_bfloat16* __restrict__ ob)
{
    extern __shared__ char sm[];
    const uint32_t sbase = smem_u32(sm);

    const int tid  = threadIdx.x;
    const int lane = tid & 31;
    const int wid  = tid >> 5;
    const int b    = blockIdx.y;
    const int q0   = blockIdx.x * 128;

    const __nv_bfloat16* Qg = qb + ((size_t)b * NN + q0) * 256;
    const __nv_bfloat16* Kg = kb + (size_t)b * NN * 256;
    const __nv_bfloat16* Vg = vb + (size_t)b * CC * NN;

#pragma unroll
    for (int tt = 0; tt < 16; tt++) {
        int idx = tid + tt * 256;
        int r = idx >> 5, ch = idx & 31;
        *reinterpret_cast<uint4*>(sm + SQ_OFF + r * QSTB + ch * 16) =
            *reinterpret_cast<const uint4*>(Qg + (size_t)r * 256 + ch * 8);
    }

    const int kr = tid >> 5, kch = tid & 31;
    const int vc = tid >> 3, vch = tid & 7;

    {
        const uint32_t kd = sbase + SK_OFF;
        const uint32_t vd = sbase + SV_OFF;
#pragma unroll
        for (int tt = 0; tt < 8; tt++) {
            int r = kr + tt * 8;
            CP_ASYNC16(kd + r * QSTB + kch * 16, Kg + (size_t)r * 256 + kch * 8);
        }
#pragma unroll
        for (int tt = 0; tt < 8; tt++) {
            int c = vc + tt * 32;
            CP_ASYNC16(vd + c * VSTB + vch * 16, Vg + (size_t)c * NN + vch * 8);
        }
        CP_COMMIT();
    }

    const int lrow = ((lane >> 3) & 1) * 8 + (lane & 7);
    const int loff = ((lane >> 4) & 1) * 16;
    const uint32_t aQ = sbase + SQ_OFF + (wid * 16 + lrow) * QSTB + loff;

    float4 oacc[32];
#pragma unroll
    for (int j = 0; j < 32; j++) oacc[j] = make_float4(0.f, 0.f, 0.f, 0.f);
    float m0r = -1e30f, m1r = -1e30f, l0r = 0.f, l1r = 0.f;

    for (int kt = 0; kt < 64; kt++) {
        const int cur = kt & 1;
        if (kt < 63) {
            const int k0n = (kt + 1) * 64;
            const uint32_t kd = sbase + SK_OFF + (cur ^ 1) * SK_BUF;
            const uint32_t vd = sbase + SV_OFF + (cur ^ 1) * SV_BUF;
#pragma unroll
            for (int tt = 0; tt < 8; tt++) {
                int r = kr + tt * 8;
                CP_ASYNC16(kd + r * QSTB + kch * 16,
                           Kg + (size_t)(k0n + r) * 256 + kch * 8);
            }
#pragma unroll
            for (int tt = 0; tt < 8; tt++) {
                int c = vc + tt * 32;
                CP_ASYNC16(vd + c * VSTB + vch * 16,
                           Vg + (size_t)c * NN + k0n + vch * 8);
            }
            CP_COMMIT();
            CP_WAIT(1);
        } else {
            CP_WAIT(0);
        }
        __syncthreads();

        const uint32_t bK = sbase + SK_OFF + cur * SK_BUF + lrow * QSTB + loff;
        const uint32_t bV = sbase + SV_OFF + cur * SV_BUF + lrow * VSTB + loff;

        float4 d[8];
#pragma unroll
        for (int j = 0; j < 8; j++) d[j] = make_float4(0.f, 0.f, 0.f, 0.f);
#pragma unroll 4
        for (int kc = 0; kc < 16; kc++) {
            uint32_t a0, a1, a2, a3;
            ldsm_x4(a0, a1, a2, a3, aQ + kc * 32);
#pragma unroll
            for (int ng = 0; ng < 4; ng++) {
                uint32_t b0, b1, b2, b3;
                ldsm_x4(b0, b1, b2, b3, bK + ng * (16 * QSTB) + kc * 32);
                mma_bf16(d[2 * ng],     a0, a1, a2, a3, b0, b2);
                mma_bf16(d[2 * ng + 1], a0, a1, a2, a3, b1, b3);
            }
        }

        float nm0 = -1e30f, nm1 = -1e30f;
#pragma unroll
        for (int j = 0; j < 8; j++) {
            nm0 = fmaxf(nm0, fmaxf(d[j].x, d[j].y));
            nm1 = fmaxf(nm1, fmaxf(d[j].z, d[j].w));
        }
        nm0 = fmaxf(nm0, __shfl_xor_sync(0xffffffffu, nm0, 1));
        nm0 = fmaxf(nm0, __shfl_xor_sync(0xffffffffu, nm0, 2));
        nm1 = fmaxf(nm1, __shfl_xor_sync(0xffffffffu, nm1, 1));
        nm1 = fmaxf(nm1, __shfl_xor_sync(0xffffffffu, nm1, 2));
        nm0 = fmaxf(m0r, nm0);
        nm1 = fmaxf(m1r, nm1);
        const float al0 = ex2f(m0r - nm0);
        const float al1 = ex2f(m1r - nm1);
        m0r = nm0; m1r = nm1;

        uint32_t pa[4][4];
        float ls0 = 0.f, ls1 = 0.f;
#pragma unroll
        for (int kc = 0; kc < 4; kc++) {
            float p00 = ex2f(d[2 * kc].x - nm0), p01 = ex2f(d[2 * kc].y - nm0);
            float p02 = ex2f(d[2 * kc].z - nm1), p03 = ex2f(d[2 * kc].w - nm1);
            float p10 = ex2f(d[2 * kc + 1].x - nm0), p11 = ex2f(d[2 * kc + 1].y - nm0);
            float p12 = ex2f(d[2 * kc + 1].z - nm1), p13 = ex2f(d[2 * kc + 1].w - nm1);
            ls0 += (p00 + p01) + (p10 + p11);
            ls1 += (p02 + p03) + (p12 + p13);
            pa[kc][0] = pack_bf16x2(p00, p01);
            pa[kc][1] = pack_bf16x2(p02, p03);
            pa[kc][2] = pack_bf16x2(p10, p11);
            pa[kc][3] = pack_bf16x2(p12, p13);
        }
        l0r = l0r * al0 + ls0;
        l1r = l1r * al1 + ls1;

        if (!__all_sync(0xffffffffu, (al0 == 1.f) & (al1 == 1.f))) {
#pragma unroll
            for (int j = 0; j < 32; j++) {
                oacc[j].x *= al0; oacc[j].y *= al0;
                oacc[j].z *= al1; oacc[j].w *= al1;
            }
        }

#pragma unroll 4
        for (int cg = 0; cg < 16; cg++) {
#pragma unroll
            for (int kc = 0; kc < 4; kc++) {
                uint32_t b0, b1, b2, b3;
                ldsm_x4(b0, b1, b2, b3, bV + cg * (16 * VSTB) + kc * 32);
                mma_bf16(oacc[2 * cg],     pa[kc][0], pa[kc][1], pa[kc][2], pa[kc][3], b0, b2);
                mma_bf16(oacc[2 * cg + 1], pa[kc][0], pa[kc][1], pa[kc][2], pa[kc][3], b1, b3);
            }
        }
        __syncthreads();
    }

    l0r += __shfl_xor_sync(0xffffffffu, l0r, 1);
    l0r += __shfl_xor_sync(0xffffffffu, l0r, 2);
    l1r += __shfl_xor_sync(0xffffffffu, l1r, 1);
    l1r += __shfl_xor_sync(0xffffffffu, l1r, 2);

    // ---- epilogue: O / l -> bf16 [b][n][c] for proj consumption ----
    const float inv0 = __frcp_rn(l0r);
    const float inv1 = __frcp_rn(l1r);
    const int g = lane >> 2, t = lane & 3;
    const int qr0 = q0 + wid * 16 + g;
    const int qr1 = qr0 + 8;
    __nv_bfloat16* r0p = ob + ((size_t)b * NN + qr0) * CC;
    __nv_bfloat16* r1p = ob + ((size_t)b * NN + qr1) * CC;
#pragma unroll
    for (int j = 0; j < 32; j++) {
        const int c = 8 * j + t * 2;
        *reinterpret_cast<uint32_t*>(r0p + c) =
            pack_bf16x2(oacc[j].x * inv0, oacc[j].y * inv0);
        *reinterpret_cast<uint32_t*>(r1p + c) =
            pack_bf16x2(oacc[j].z * inv1, oacc[j].w * inv1);
    }
}

// ================================ launch ====================================
extern "C" void kernel_launch(void* const* d_in, const int* in_sizes, int n_in,
                              void* d_out, int out_size)
{
    const float* x     = (const float*)d_in[0];
    const float* nw    = (const float*)d_in[1];
    const float* nb    = (const float*)d_in[2];
    const float* qkvw  = (const float*)d_in[3];
    const float* qkvb  = (const float*)d_in[4];
    const float* projw = (const float*)d_in[5];
    const float* projb = (const float*)d_in[6];
    float* out = (float*)d_out;

    float* hbuf;
    __nv_bfloat16 *htp, *wqp, *wpp, *qbp, *kbp, *vbp, *obp;
    cudaGetSymbolAddress((void**)&hbuf, g_h);
    cudaGetSymbolAddress((void**)&htp, g_ht);
    cudaGetSymbolAddress((void**)&wqp, g_wq);
    cudaGetSymbolAddress((void**)&wpp, g_wp);
    cudaGetSymbolAddress((void**)&qbp, g_qb);
    cudaGetSymbolAddress((void**)&kbp, g_kb);
    cudaGetSymbolAddress((void**)&vbp, g_vb);
    cudaGetSymbolAddress((void**)&obp, g_ob);

    cudaFuncSetAttribute(attn5_kernel, cudaFuncAttributeMaxDynamicSharedMemorySize,
                         ATT_SMEM);
    cudaFuncSetAttribute(tgemm_kernel, cudaFuncAttributeMaxDynamicSharedMemorySize,
                         TG_SMEM);

    gn_kernel<<<dim3(GG, BB), 256>>>(x, nw, nb, hbuf);
    wconv_kernel<<<(768 * 256 + 256 * 256) / 256, 256>>>(qkvw, projw, wqp, wpp);
    ht_kernel<<<dim3(NN / 32, CC / 32, BB), 256>>>(hbuf, htp);
    tgemm_kernel<<<dim3(NN / 128, 12, BB), 256, TG_SMEM>>>(
        wqp, htp, qkvb, nullptr, qbp, kbp, vbp, nullptr, 0);
    attn5_kernel<<<dim3(NN / 128, BB), 256, ATT_SMEM>>>(qbp, kbp, vbp, obp);
    tgemm_kernel<<<dim3(NN / 128, 4, BB), 256, TG_SMEM>>>(
        wpp, obp, projb, x, nullptr, nullptr, nullptr, out, 1);
}